// round 15
// baseline (speedup 1.0000x reference)
#include <cuda_runtime.h>
#include <cuda_bf16.h>
#include <cstdint>
#include <math.h>

#define NROWS 4096      // B*T
#define CDIM  1024
#define HDIM  64
#define NHEADS 16
#define TSEQ  1024
#define FFDIM 4096

// ================= helpers ==================================================
__device__ __forceinline__ uint32_t smem_to_u32(const void* p) {
    uint32_t a;
    asm("{ .reg .u64 t; cvta.to.shared.u64 t, %1; cvt.u32.u64 %0, t; }"
        : "=r"(a) : "l"(p));
    return a;
}
__device__ __forceinline__ void ldsm_x4(uint32_t& r0, uint32_t& r1,
                                        uint32_t& r2, uint32_t& r3, uint32_t a) {
    asm volatile("ldmatrix.sync.aligned.m8n8.x4.shared.b16 {%0,%1,%2,%3}, [%4];"
                 : "=r"(r0), "=r"(r1), "=r"(r2), "=r"(r3) : "r"(a));
}
__device__ __forceinline__ void ldsm_x4_trans(uint32_t& r0, uint32_t& r1,
                                              uint32_t& r2, uint32_t& r3, uint32_t a) {
    asm volatile("ldmatrix.sync.aligned.m8n8.x4.trans.shared.b16 {%0,%1,%2,%3}, [%4];"
                 : "=r"(r0), "=r"(r1), "=r"(r2), "=r"(r3) : "r"(a));
}
__device__ __forceinline__ void mma_bf16(float* d,
                                         uint32_t a0, uint32_t a1, uint32_t a2, uint32_t a3,
                                         uint32_t b0, uint32_t b1) {
    asm volatile("mma.sync.aligned.m16n8k16.row.col.f32.bf16.bf16.f32 "
                 "{%0,%1,%2,%3}, {%4,%5,%6,%7}, {%8,%9}, {%0,%1,%2,%3};"
                 : "+f"(d[0]), "+f"(d[1]), "+f"(d[2]), "+f"(d[3])
                 : "r"(a0), "r"(a1), "r"(a2), "r"(a3), "r"(b0), "r"(b1));
}
#define CP_ASYNC16(dst, src) \
    asm volatile("cp.async.cg.shared.global [%0], [%1], 16;" :: "r"(dst), "l"(src))
#define CP_COMMIT() asm volatile("cp.async.commit_group;" ::: "memory")
#define CP_WAIT0()  asm volatile("cp.async.wait_group 0;" ::: "memory")
#define CP_WAIT1()  asm volatile("cp.async.wait_group 1;" ::: "memory")

__device__ __forceinline__ void split_bf16(float v, __nv_bfloat16& h, __nv_bfloat16& l) {
    h = __float2bfloat16(v);
    l = __float2bfloat16(v - __bfloat162float(h));
}
__device__ __forceinline__ uint32_t packh(__nv_bfloat16 a, __nv_bfloat16 b) {
    __nv_bfloat162 t; t.x = a; t.y = b;
    return *(uint32_t*)&t;
}
__device__ __forceinline__ void splitpack(float v0, float v1, uint32_t& ph, uint32_t& pl) {
    __nv_bfloat16 h0 = __float2bfloat16(v0), h1 = __float2bfloat16(v1);
    ph = packh(h0, h1);
    float l0 = v0 - __bfloat162float(h0), l1 = v1 - __bfloat162float(h1);
    asm("cvt.rn.bf16x2.f32 %0, %1, %2;" : "=r"(pl) : "f"(l1), "f"(l0));
}
__device__ __forceinline__ float gelu_exact(float v) {
    return 0.5f * v * (1.0f + erff(v * 0.70710678118654752f));
}

// ================= scratch ==================================================
#define MB (1024ull * 1024ull)
__device__ __align__(1024) unsigned char g_scratch[225 * MB];
#define OFF_QH    (0 * MB)
#define OFF_QL    (8 * MB)
#define OFF_KH    (16 * MB)
#define OFF_KL    (24 * MB)
#define OFF_VH    (32 * MB)
#define OFF_VL    (40 * MB)
#define OFF_Y     (48 * MB)
#define OFF_LN1H  (64 * MB)
#define OFF_LN1L  (72 * MB)
#define OFF_ATTH  (80 * MB)
#define OFF_ATTL  (88 * MB)
#define OFF_LN2H  (96 * MB)
#define OFF_LN2L  (104 * MB)
#define OFF_FFH   (112 * MB)
#define OFF_FFL   (144 * MB)
#define OFF_WQKVH (176 * MB)
#define OFF_WQKVL (182 * MB)
#define OFF_WPH   (188 * MB)
#define OFF_WPL   (190 * MB)
#define OFF_W1H   (192 * MB)
#define OFF_W1L   (200 * MB)
#define OFF_W2H   (208 * MB)
#define OFF_W2L   (216 * MB)
#define OFF_BIASC (224 * MB)
#define QKV_SEL_STRIDE 8388608ull

// ================= bias concat ==============================================
__global__ __launch_bounds__(1024) void bias_concat_kernel(
    const float* __restrict__ bq, const float* __restrict__ bk,
    const float* __restrict__ bv, float* __restrict__ dst) {
    int i = threadIdx.x;
    const float* src = (blockIdx.x == 0) ? bq : (blockIdx.x == 1) ? bk : bv;
    dst[blockIdx.x * 1024 + i] = src[i];
}

// ================= fused weight convert+transpose (ALL weights) =============
__global__ __launch_bounds__(256) void wconv_all(
    const float* __restrict__ Wq, const float* __restrict__ Wk,
    const float* __restrict__ Wv, const float* __restrict__ Wp,
    const float* __restrict__ W1, const float* __restrict__ W2,
    __nv_bfloat16* __restrict__ qkvh, __nv_bfloat16* __restrict__ qkvl,
    __nv_bfloat16* __restrict__ wph,  __nv_bfloat16* __restrict__ wpl,
    __nv_bfloat16* __restrict__ w1h,  __nv_bfloat16* __restrict__ w1l,
    __nv_bfloat16* __restrict__ w2h,  __nv_bfloat16* __restrict__ w2l) {
    int bid = blockIdx.x;
    const float* W; __nv_bfloat16 *Wh, *Wl;
    int K, N, bx, by;
    if (bid < 768) {
        int which = bid >> 8;
        int idx = bid & 255;
        W = (which == 0) ? Wq : (which == 1) ? Wk : Wv;
        Wh = qkvh + (size_t)which * 1024 * 1024;
        Wl = qkvl + (size_t)which * 1024 * 1024;
        K = 1024; N = 1024; bx = idx & 15; by = idx >> 4;
    } else if (bid < 1024) {
        int idx = bid - 768;
        W = Wp; Wh = wph; Wl = wpl;
        K = 1024; N = 1024; bx = idx & 15; by = idx >> 4;
    } else if (bid < 2048) {
        int idx = bid - 1024;
        W = W1; Wh = w1h; Wl = w1l;
        K = 1024; N = 4096; bx = idx & 15; by = idx >> 4;
    } else {
        int idx = bid - 2048;
        W = W2; Wh = w2h; Wl = w2l;
        K = 4096; N = 1024; bx = idx & 63; by = idx >> 6;
    }

    __shared__ float t[64][65];
    int k0 = bx * 64, n0 = by * 64;
    int tid = threadIdx.x;
    #pragma unroll
    for (int i = 0; i < 16; i++) {
        int idx = i * 256 + tid;
        int r = idx >> 6, c = idx & 63;
        t[r][c] = W[(size_t)(k0 + r) * N + n0 + c];
    }
    __syncthreads();
    #pragma unroll
    for (int i = 0; i < 16; i++) {
        int idx = i * 256 + tid;
        int r = idx >> 6, c = idx & 63;
        float v = t[c][r];
        __nv_bfloat16 h, l;
        split_bf16(v, h, l);
        size_t o = (size_t)(n0 + r) * K + k0 + c;
        Wh[o] = h; Wl[o] = l;
    }
}

// ================= layernorm -> bf16 hi/lo ==================================
__global__ __launch_bounds__(256) void ln_kernel(const float* __restrict__ x,
                                                 const float* __restrict__ g,
                                                 const float* __restrict__ b,
                                                 __nv_bfloat16* __restrict__ H,
                                                 __nv_bfloat16* __restrict__ L) {
    int row = blockIdx.x;
    int t = threadIdx.x;
    const float4* xr = (const float4*)(x + (size_t)row * CDIM);
    float4 xv = xr[t];
    float s  = xv.x + xv.y + xv.z + xv.w;
    float ss = xv.x * xv.x + xv.y * xv.y + xv.z * xv.z + xv.w * xv.w;
    #pragma unroll
    for (int m = 16; m; m >>= 1) {
        s  += __shfl_xor_sync(0xffffffffu, s,  m);
        ss += __shfl_xor_sync(0xffffffffu, ss, m);
    }
    __shared__ float rs[8], rss[8];
    int warp = t >> 5, lane = t & 31;
    if (lane == 0) { rs[warp] = s; rss[warp] = ss; }
    __syncthreads();
    float tot = 0.f, tots = 0.f;
    #pragma unroll
    for (int i = 0; i < 8; i++) { tot += rs[i]; tots += rss[i]; }
    float mu  = tot * (1.0f / CDIM);
    float var = tots * (1.0f / CDIM) - mu * mu;
    float inv = rsqrtf(var + 1e-5f);
    float4 gv = ((const float4*)g)[t];
    float4 bv = ((const float4*)b)[t];
    float o0 = (xv.x - mu) * inv * gv.x + bv.x;
    float o1 = (xv.y - mu) * inv * gv.y + bv.y;
    float o2 = (xv.z - mu) * inv * gv.z + bv.z;
    float o3 = (xv.w - mu) * inv * gv.w + bv.w;
    __nv_bfloat16 h0, h1, h2, h3, l0, l1, l2, l3;
    split_bf16(o0, h0, l0); split_bf16(o1, h1, l1);
    split_bf16(o2, h2, l2); split_bf16(o3, h3, l3);
    __nv_bfloat162* Hp = (__nv_bfloat162*)(H + (size_t)row * CDIM + t * 4);
    __nv_bfloat162* Lp = (__nv_bfloat162*)(L + (size_t)row * CDIM + t * 4);
    __nv_bfloat162 a01; a01.x = h0; a01.y = h1;
    __nv_bfloat162 a23; a23.x = h2; a23.y = h3;
    __nv_bfloat162 b01; b01.x = l0; b01.y = l1;
    __nv_bfloat162 b23; b23.x = l2; b23.y = l3;
    Hp[0] = a01; Hp[1] = a23;
    Lp[0] = b01; Lp[1] = b23;
}

// ================= HMMA bf16x3 GEMM (128x128 CTA, 8 warps, 3-stage pipe) ====
// 256 threads, warp tile 32x64 (R11 layout). 3 smem stages, cp.async 2 ahead.
#define TSTR 80
#define TILE_B (128 * TSTR)            // 10240
#define BUF_B  (4 * TILE_B)            // 40960
#define GEMM_SMEM (3 * BUF_B)          // 122880

__global__ __launch_bounds__(256) void gemm_tc(
    const __nv_bfloat16* __restrict__ Ah, const __nv_bfloat16* __restrict__ Al,
    const __nv_bfloat16* __restrict__ Bh, const __nv_bfloat16* __restrict__ Bl,
    const float* __restrict__ bias, const float* __restrict__ R,
    float* __restrict__ outF, __nv_bfloat16* __restrict__ outH,
    __nv_bfloat16* __restrict__ outL, int K, int N, int act, int qkv) {
    extern __shared__ char sm[];
    uint32_t sbase = smem_to_u32(sm);
    int tid = threadIdx.x;
    int wid = tid >> 5, lane = tid & 31;
    int warp_m = wid & 3, warp_n = wid >> 2;
    int bx = blockIdx.x;
    int wrow0 = bx * 128;
    int n0 = qkv ? ((bx & 7) * 128) : wrow0;
    const float* biasP = bias + (qkv ? bx * 128 : n0);
    size_t osel = qkv ? (size_t)(bx >> 3) * QKV_SEL_STRIDE : 0;
    int m0 = blockIdx.y * 128;
    int NC = K >> 5;

    float acc[2][8][4];
    #pragma unroll
    for (int i = 0; i < 2; i++)
        #pragma unroll
        for (int j = 0; j < 8; j++)
            #pragma unroll
            for (int c = 0; c < 4; c++) acc[i][j][c] = 0.f;

    const __nv_bfloat16* tiles[4] = {Ah, Al, Bh, Bl};
    int row0s[4] = {m0, m0, wrow0, wrow0};
    int ldr = tid >> 2;   // 0..63
    int ldc = tid & 3;

    // prologue: issue chunks 0 and 1 into stages 0,1
    #pragma unroll
    for (int pc = 0; pc < 2; pc++) {
        uint32_t dbuf = sbase + pc * BUF_B;
        int k0 = pc * 32;
        #pragma unroll
        for (int t = 0; t < 4; t++)
            #pragma unroll
            for (int it = 0; it < 2; it++) {
                int r = it * 64 + ldr;
                uint32_t dst = dbuf + t * TILE_B + r * TSTR + ldc * 16;
                const __nv_bfloat16* src = tiles[t] + (size_t)(row0s[t] + r) * K + k0 + ldc * 8;
                CP_ASYNC16(dst, src);
            }
        CP_COMMIT();
    }
    CP_WAIT1();            // chunk 0 landed (chunk 1 may be in flight)
    __syncthreads();

    int a_row = (lane & 7) + ((lane >> 3) & 1) * 8;
    int a_kb  = ((lane >> 4) & 1) * 16;
    int b_row = (lane & 7) + ((lane >> 4) & 1) * 8;
    int b_kb  = ((lane >> 3) & 1) * 16;

    int sidx = 0;          // stage holding chunk kc
    for (int kc = 0; kc < NC; kc++) {
        uint32_t sbuf = sbase + sidx * BUF_B;
        // issue chunk kc+2 into the stage after next ((sidx+2)%3) — that stage
        // held chunk kc-1, fully consumed before the barrier at end of kc-1.
        if (kc + 2 < NC) {
            int ds = sidx + 2; if (ds >= 3) ds -= 3;
            uint32_t dbuf = sbase + ds * BUF_B;
            int k0 = (kc + 2) * 32;
            #pragma unroll
            for (int t = 0; t < 4; t++)
                #pragma unroll
                for (int it = 0; it < 2; it++) {
                    int r = it * 64 + ldr;
                    uint32_t dst = dbuf + t * TILE_B + r * TSTR + ldc * 16;
                    const __nv_bfloat16* src = tiles[t] + (size_t)(row0s[t] + r) * K + k0 + ldc * 8;
                    CP_ASYNC16(dst, src);
                }
            CP_COMMIT();
        }

        #pragma unroll
        for (int ks = 0; ks < 2; ks++) {
            int kb = ks * 32;
            uint32_t ah[2][4], al[2][4];
            #pragma unroll
            for (int mt = 0; mt < 2; mt++) {
                uint32_t addr = sbuf + (warp_m * 32 + mt * 16 + a_row) * TSTR + kb + a_kb;
                ldsm_x4(ah[mt][0], ah[mt][1], ah[mt][2], ah[mt][3], addr);
                ldsm_x4(al[mt][0], al[mt][1], al[mt][2], al[mt][3], addr + TILE_B);
            }
            #pragma unroll
            for (int nb = 0; nb < 4; nb++) {
                uint32_t addr = sbuf + 2 * TILE_B +
                                (warp_n * 64 + nb * 16 + b_row) * TSTR + kb + b_kb;
                uint32_t bh0, bh1, bh2, bh3, bl0, bl1, bl2, bl3;
                ldsm_x4(bh0, bh1, bh2, bh3, addr);
                ldsm_x4(bl0, bl1, bl2, bl3, addr + TILE_B);
                #pragma unroll
                for (int mt = 0; mt < 2; mt++) {
                    float* e = acc[mt][nb * 2];
                    float* o = acc[mt][nb * 2 + 1];
                    mma_bf16(e, ah[mt][0], ah[mt][1], ah[mt][2], ah[mt][3], bh0, bh1);
                    mma_bf16(e, ah[mt][0], ah[mt][1], ah[mt][2], ah[mt][3], bl0, bl1);
                    mma_bf16(e, al[mt][0], al[mt][1], al[mt][2], al[mt][3], bh0, bh1);
                    mma_bf16(o, ah[mt][0], ah[mt][1], ah[mt][2], ah[mt][3], bh2, bh3);
                    mma_bf16(o, ah[mt][0], ah[mt][1], ah[mt][2], ah[mt][3], bl2, bl3);
                    mma_bf16(o, al[mt][0], al[mt][1], al[mt][2], al[mt][3], bh2, bh3);
                }
            }
        }

        // ensure chunk kc+1 has landed (kc+2 may remain in flight), then sync.
        if (kc + 1 < NC) {
            if (kc + 2 < NC) CP_WAIT1();
            else CP_WAIT0();
            __syncthreads();
        }
        sidx++; if (sidx >= 3) sidx -= 3;
    }

    #pragma unroll
    for (int mt = 0; mt < 2; mt++) {
        #pragma unroll
        for (int nt = 0; nt < 8; nt++) {
            int cl = warp_n * 64 + nt * 8 + (lane & 3) * 2;
            int col = n0 + cl;
            #pragma unroll
            for (int half = 0; half < 2; half++) {
                int row = m0 + warp_m * 32 + mt * 16 + (lane >> 2) + half * 8;
                float v0 = acc[mt][nt][half * 2 + 0] + biasP[cl + 0];
                float v1 = acc[mt][nt][half * 2 + 1] + biasP[cl + 1];
                if (outF) {
                    if (R) {
                        const float2 rv = *(const float2*)(R + (size_t)row * N + col);
                        v0 += rv.x; v1 += rv.y;
                    }
                    float2 o2; o2.x = v0; o2.y = v1;
                    *(float2*)(outF + (size_t)row * N + col) = o2;
                } else {
                    if (act) { v0 = gelu_exact(v0); v1 = gelu_exact(v1); }
                    __nv_bfloat16 h0, h1, l0, l1;
                    split_bf16(v0, h0, l0);
                    split_bf16(v1, h1, l1);
                    __nv_bfloat162 hh; hh.x = h0; hh.y = h1;
                    __nv_bfloat162 ll; ll.x = l0; ll.y = l1;
                    *(__nv_bfloat162*)(outH + osel + (size_t)row * N + col) = hh;
                    *(__nv_bfloat162*)(outL + osel + (size_t)row * N + col) = ll;
                }
            }
        }
    }
}

// ================= HMMA flash attention =====================================
#define ATS 144
#define ATTN_SMEM (2 * 128 * ATS + 4 * 64 * ATS)

__global__ __launch_bounds__(256) void attn_tc(
    const __nv_bfloat16* __restrict__ qh, const __nv_bfloat16* __restrict__ ql,
    const __nv_bfloat16* __restrict__ kh, const __nv_bfloat16* __restrict__ kl,
    const __nv_bfloat16* __restrict__ vh, const __nv_bfloat16* __restrict__ vl,
    __nv_bfloat16* __restrict__ oh, __nv_bfloat16* __restrict__ ol) {
    extern __shared__ char sm[];
    uint32_t sb = smem_to_u32(sm);
    uint32_t sQh = sb;
    uint32_t sQl = sb + 128 * ATS;
    uint32_t sKh = sb + 2 * 128 * ATS;
    uint32_t sKl = sKh + 64 * ATS;
    uint32_t sVh = sKl + 64 * ATS;
    uint32_t sVl = sVh + 64 * ATS;

    int qb = gridDim.x - 1 - blockIdx.x;   // LPT
    int bh = blockIdx.y;
    int b = bh >> 4, h = bh & 15;
    int q0 = qb * 128;
    int tid = threadIdx.x, wid = tid >> 5, lane = tid & 31;
    int g = lane >> 2, t4 = lane & 3;

    size_t base = ((size_t)b * TSEQ) * CDIM + (size_t)h * HDIM;

    #pragma unroll
    for (int i = 0; i < 4; i++) {
        int idx = i * 256 + tid;
        int r = idx >> 3, c = idx & 7;
        size_t gsrc = base + (size_t)(q0 + r) * CDIM + c * 8;
        CP_ASYNC16(sQh + r * ATS + c * 16, qh + gsrc);
        CP_ASYNC16(sQl + r * ATS + c * 16, ql + gsrc);
    }
    CP_COMMIT();
    CP_WAIT0();
    __syncthreads();

    int a_row = (lane & 7) + ((lane >> 3) & 1) * 8;
    int a_kb  = ((lane >> 4) & 1) * 16;
    int b_row = (lane & 7) + ((lane >> 4) & 1) * 8;
    int b_kb  = ((lane >> 3) & 1) * 16;
    int v_row = (lane & 7) + ((lane >> 3) & 1) * 8;
    int v_cb  = ((lane >> 4) & 1) * 16;

    uint32_t qfh[4][4], qfl[4][4];
    #pragma unroll
    for (int ks = 0; ks < 4; ks++) {
        uint32_t ad = sQh + (wid * 16 + a_row) * ATS + ks * 32 + a_kb;
        ldsm_x4(qfh[ks][0], qfh[ks][1], qfh[ks][2], qfh[ks][3], ad);
        ldsm_x4(qfl[ks][0], qfl[ks][1], qfl[ks][2], qfl[ks][3], ad + 128 * ATS);
    }

    float oacc[8][4];
    #pragma unroll
    for (int i = 0; i < 8; i++)
        #pragma unroll
        for (int c = 0; c < 4; c++) oacc[i][c] = 0.f;
    float mrun0 = -1e30f, mrun1 = -1e30f, lrun0 = 0.f, lrun1 = 0.f;

    int nkt = 2 * qb + 2;
    for (int kt = 0; kt < nkt; kt++) {
        __syncthreads();
        #pragma unroll
        for (int i = 0; i < 2; i++) {
            int idx = i * 256 + tid;
            int r = idx >> 3, c = idx & 7;
            size_t gsrc = base + (size_t)(kt * 64 + r) * CDIM + c * 8;
            uint32_t so = r * ATS + c * 16;
            CP_ASYNC16(sKh + so, kh + gsrc);
            CP_ASYNC16(sKl + so, kl + gsrc);
            CP_ASYNC16(sVh + so, vh + gsrc);
            CP_ASYNC16(sVl + so, vl + gsrc);
        }
        CP_COMMIT();
        CP_WAIT0();
        __syncthreads();

        float sacc[8][4];
        #pragma unroll
        for (int i = 0; i < 8; i++)
            #pragma unroll
            for (int c = 0; c < 4; c++) sacc[i][c] = 0.f;

        #pragma unroll
        for (int kg = 0; kg < 4; kg++) {
            #pragma unroll
            for (int ks = 0; ks < 4; ks++) {
                uint32_t ad = sKh + (kg * 16 + b_row) * ATS + ks * 32 + b_kb;
                uint32_t kh0, kh1, kh2, kh3, kl0, kl1, kl2, kl3;
                ldsm_x4(kh0, kh1, kh2, kh3, ad);
                ldsm_x4(kl0, kl1, kl2, kl3, ad + 64 * ATS);
                float* e = sacc[kg * 2];
                float* o = sacc[kg * 2 + 1];
                mma_bf16(e, qfh[ks][0], qfh[ks][1], qfh[ks][2], qfh[ks][3], kh0, kh1);
                mma_bf16(e, qfh[ks][0], qfh[ks][1], qfh[ks][2], qfh[ks][3], kl0, kl1);
                mma_bf16(e, qfl[ks][0], qfl[ks][1], qfl[ks][2], qfl[ks][3], kh0, kh1);
                mma_bf16(o, qfh[ks][0], qfh[ks][1], qfh[ks][2], qfh[ks][3], kh2, kh3);
                mma_bf16(o, qfh[ks][0], qfh[ks][1], qfh[ks][2], qfh[ks][3], kl2, kl3);
                mma_bf16(o, qfl[ks][0], qfl[ks][1], qfl[ks][2], qfl[ks][3], kh2, kh3);
            }
        }

        int r0g = q0 + wid * 16 + g;
        int r1g = r0g + 8;
        bool maskt = (kt >= 2 * qb);
        #pragma unroll
        for (int nt = 0; nt < 8; nt++) {
            #pragma unroll
            for (int c = 0; c < 4; c++) sacc[nt][c] *= 0.125f;
            if (maskt) {
                int cb = kt * 64 + nt * 8 + 2 * t4;
                if (cb     > r0g) sacc[nt][0] = -1e30f;
                if (cb + 1 > r0g) sacc[nt][1] = -1e30f;
                if (cb     > r1g) sacc[nt][2] = -1e30f;
                if (cb + 1 > r1g) sacc[nt][3] = -1e30f;
            }
        }

        float mt0 = -1e30f, mt1 = -1e30f;
        #pragma unroll
        for (int nt = 0; nt < 8; nt++) {
            mt0 = fmaxf(mt0, fmaxf(sacc[nt][0], sacc[nt][1]));
            mt1 = fmaxf(mt1, fmaxf(sacc[nt][2], sacc[nt][3]));
        }
        mt0 = fmaxf(mt0, __shfl_xor_sync(0xffffffffu, mt0, 1));
        mt0 = fmaxf(mt0, __shfl_xor_sync(0xffffffffu, mt0, 2));
        mt1 = fmaxf(mt1, __shfl_xor_sync(0xffffffffu, mt1, 1));
        mt1 = fmaxf(mt1, __shfl_xor_sync(0xffffffffu, mt1, 2));

        float mn0 = fmaxf(mrun0, mt0), mn1 = fmaxf(mrun1, mt1);
        float cr0 = __expf(mrun0 - mn0), cr1 = __expf(mrun1 - mn1);
        mrun0 = mn0; mrun1 = mn1;
        #pragma unroll
        for (int nt = 0; nt < 8; nt++) {
            oacc[nt][0] *= cr0; oacc[nt][1] *= cr0;
            oacc[nt][2] *= cr1; oacc[nt][3] *= cr1;
        }
        lrun0 *= cr0; lrun1 *= cr1;

        float ls0 = 0.f, ls1 = 0.f;
        #pragma unroll
        for (int nt = 0; nt < 8; nt++) {
            sacc[nt][0] = __expf(sacc[nt][0] - mn0);
            sacc[nt][1] = __expf(sacc[nt][1] - mn0);
            sacc[nt][2] = __expf(sacc[nt][2] - mn1);
            sacc[nt][3] = __expf(sacc[nt][3] - mn1);
            ls0 += sacc[nt][0] + sacc[nt][1];
            ls1 += sacc[nt][2] + sacc[nt][3];
        }
        ls0 += __shfl_xor_sync(0xffffffffu, ls0, 1);
        ls0 += __shfl_xor_sync(0xffffffffu, ls0, 2);
        ls1 += __shfl_xor_sync(0xffffffffu, ls1, 1);
        ls1 += __shfl_xor_sync(0xffffffffu, ls1, 2);
        lrun0 += ls0; lrun1 += ls1;

        #pragma unroll
        for (int s = 0; s < 4; s++) {
            uint32_t aPh[4], aPl[4];
            splitpack(sacc[2 * s][0],     sacc[2 * s][1],     aPh[0], aPl[0]);
            splitpack(sacc[2 * s][2],     sacc[2 * s][3],     aPh[1], aPl[1]);
            splitpack(sacc[2 * s + 1][0], sacc[2 * s + 1][1], aPh[2], aPl[2]);
            splitpack(sacc[2 * s + 1][2], sacc[2 * s + 1][3], aPh[3], aPl[3]);
            #pragma unroll
            for (int p = 0; p < 4; p++) {
                uint32_t ad = sVh + (s * 16 + v_row) * ATS + p * 32 + v_cb;
                uint32_t vh0, vh1, vh2, vh3, vl0, vl1, vl2, vl3;
                ldsm_x4_trans(vh0, vh1, vh2, vh3, ad);
                ldsm_x4_trans(vl0, vl1, vl2, vl3, ad + 64 * ATS);
                float* e = oacc[p * 2];
                float* o = oacc[p * 2 + 1];
                mma_bf16(e, aPh[0], aPh[1], aPh[2], aPh[3], vh0, vh1);
                mma_bf16(e, aPl[0], aPl[1], aPl[2], aPl[3], vh0, vh1);
                mma_bf16(e, aPh[0], aPh[1], aPh[2], aPh[3], vl0, vl1);
                mma_bf16(o, aPh[0], aPh[1], aPh[2], aPh[3], vh2, vh3);
                mma_bf16(o, aPl[0], aPl[1], aPl[2], aPl[3], vh2, vh3);
                mma_bf16(o, aPh[0], aPh[1], aPh[2], aPh[3], vl2, vl3);
            }
        }
    }

    float il0 = 1.0f / lrun0, il1 = 1.0f / lrun1;
    int r0g = q0 + wid * 16 + g;
    #pragma unroll
    for (int nt = 0; nt < 8; nt++) {
        int col = nt * 8 + 2 * t4;
        float v0 = oacc[nt][0] * il0, v1 = oacc[nt][1] * il0;
        float v2 = oacc[nt][2] * il1, v3 = oacc[nt][3] * il1;
        __nv_bfloat16 h0, h1, h2, h3, l0, l1, l2, l3;
        split_bf16(v0, h0, l0); split_bf16(v1, h1, l1);
        split_bf16(v2, h2, l2); split_bf16(v3, h3, l3);
        size_t o0 = base + (size_t)r0g * CDIM + col;
        size_t o1 = base + (size_t)(r0g + 8) * CDIM + col;
        __nv_bfloat162 t;
        t.x = h0; t.y = h1; *(__nv_bfloat162*)(oh + o0) = t;
        t.x = l0; t.y = l1; *(__nv_bfloat162*)(ol + o0) = t;
        t.x = h2; t.y = h3; *(__nv_bfloat162*)(oh + o1) = t;
        t.x = l2; t.y = l3; *(__nv_bfloat162*)(ol + o1) = t;
    }
}

// ================= launch ====================================================
extern "C" void kernel_launch(void* const* d_in, const int* in_sizes, int n_in,
                              void* d_out, int out_size) {
    const float* x   = (const float*)d_in[0];
    const float* Wq  = (const float*)d_in[1];
    const float* bq  = (const float*)d_in[2];
    const float* Wk  = (const float*)d_in[3];
    const float* bk  = (const float*)d_in[4];
    const float* Wv  = (const float*)d_in[5];
    const float* bv  = (const float*)d_in[6];
    const float* Wp  = (const float*)d_in[7];
    const float* bp  = (const float*)d_in[8];
    const float* W1  = (const float*)d_in[9];
    const float* b1  = (const float*)d_in[10];
    const float* W2  = (const float*)d_in[11];
    const float* b2  = (const float*)d_in[12];
    const float* g1  = (const float*)d_in[13];
    const float* be1 = (const float*)d_in[14];
    const float* g2  = (const float*)d_in[15];
    const float* be2 = (const float*)d_in[16];
    float* out = (float*)d_out;

    unsigned char* S;
    cudaGetSymbolAddress((void**)&S, g_scratch);
    __nv_bfloat16* qhB = (__nv_bfloat16*)(S + OFF_QH);
    __nv_bfloat16* qlB = (__nv_bfloat16*)(S + OFF_QL);
    __nv_bfloat16* khB = (__nv_bfloat16*)(S + OFF_KH);
    __nv_bfloat16* klB = (__nv_bfloat16*)(S + OFF_KL);
    __nv_bfloat16* vhB = (__nv_bfloat16*)(S + OFF_VH);
    __nv_bfloat16* vlB = (__nv_bfloat16*)(S + OFF_VL);
    float* yb  = (float*)(S + OFF_Y);
    __nv_bfloat16* ln1h = (__nv_bfloat16*)(S + OFF_LN1H);
    __nv_bfloat16* ln1l = (__nv_bfloat16*)(S + OFF_LN1L);
    __nv_bfloat16* atth = (__nv_bfloat16*)(S + OFF_ATTH);
    __nv_bfloat16* attl = (__nv_bfloat16*)(S + OFF_ATTL);
    __nv_bfloat16* ln2h = (__nv_bfloat16*)(S + OFF_LN2H);
    __nv_bfloat16* ln2l = (__nv_bfloat16*)(S + OFF_LN2L);
    __nv_bfloat16* ffh  = (__nv_bfloat16*)(S + OFF_FFH);
    __nv_bfloat16* ffl  = (__nv_bfloat16*)(S + OFF_FFL);
    __nv_bfloat16* wqkvh = (__nv_bfloat16*)(S + OFF_WQKVH);
    __nv_bfloat16* wqkvl = (__nv_bfloat16*)(S + OFF_WQKVL);
    __nv_bfloat16* wph = (__nv_bfloat16*)(S + OFF_WPH);
    __nv_bfloat16* wpl = (__nv_bfloat16*)(S + OFF_WPL);
    __nv_bfloat16* w1h = (__nv_bfloat16*)(S + OFF_W1H);
    __nv_bfloat16* w1l = (__nv_bfloat16*)(S + OFF_W1L);
    __nv_bfloat16* w2h = (__nv_bfloat16*)(S + OFF_W2H);
    __nv_bfloat16* w2l = (__nv_bfloat16*)(S + OFF_W2L);
    float* biasC = (float*)(S + OFF_BIASC);

    cudaFuncSetAttribute(attn_tc, cudaFuncAttributeMaxDynamicSharedMemorySize, ATTN_SMEM);
    cudaFuncSetAttribute(gemm_tc, cudaFuncAttributeMaxDynamicSharedMemorySize, GEMM_SMEM);

    // 1: bias concat
    bias_concat_kernel<<<3, 1024>>>(bq, bk, bv, biasC);
    // 2: all weight conversions
    wconv_all<<<3072, 256>>>(Wq, Wk, Wv, Wp, W1, W2,
                             wqkvh, wqkvl, wph, wpl, w1h, w1l, w2h, w2l);
    // 3: LN1
    ln_kernel<<<NROWS, 256>>>(x, g1, be1, ln1h, ln1l);

    dim3 gQKV(24, 32);
    dim3 gQ(8, 32);
    dim3 gF1(32, 32);
    // 4: QKV
    gemm_tc<<<gQKV, 256, GEMM_SMEM>>>(ln1h, ln1l, wqkvh, wqkvl, biasC, nullptr,
                                      nullptr, qhB, qlB, 1024, 1024, 0, 1);
    // 5: attention
    attn_tc<<<dim3(TSEQ / 128, 4 * NHEADS), 256, ATTN_SMEM>>>(qhB, qlB, khB, klB, vhB, vlB, atth, attl);
    // 6: proj (ncu -s 5 -c 1 lands here)
    gemm_tc<<<gQ, 256, GEMM_SMEM>>>(atth, attl, wph, wpl, bp, x, yb, nullptr, nullptr, 1024, 1024, 0, 0);
    // 7: LN2
    ln_kernel<<<NROWS, 256>>>(yb, g2, be2, ln2h, ln2l);
    // 8: FF1
    gemm_tc<<<gF1, 256, GEMM_SMEM>>>(ln2h, ln2l, w1h, w1l, b1, nullptr, nullptr, ffh, ffl, 1024, 4096, 1, 0);
    // 9: FF2
    gemm_tc<<<gQ, 256, GEMM_SMEM>>>(ffh, ffl, w2h, w2l, b2, yb, out, nullptr, nullptr, 4096, 1024, 0, 0);
}

// round 16
// speedup vs baseline: 1.2127x; 1.2127x over previous
#include <cuda_runtime.h>
#include <cuda_bf16.h>
#include <cstdint>
#include <math.h>

#define NROWS 4096      // B*T
#define CDIM  1024
#define HDIM  64
#define NHEADS 16
#define TSEQ  1024
#define FFDIM 4096

// ================= helpers ==================================================
__device__ __forceinline__ uint32_t smem_to_u32(const void* p) {
    uint32_t a;
    asm("{ .reg .u64 t; cvta.to.shared.u64 t, %1; cvt.u32.u64 %0, t; }"
        : "=r"(a) : "l"(p));
    return a;
}
__device__ __forceinline__ void ldsm_x4(uint32_t& r0, uint32_t& r1,
                                        uint32_t& r2, uint32_t& r3, uint32_t a) {
    asm volatile("ldmatrix.sync.aligned.m8n8.x4.shared.b16 {%0,%1,%2,%3}, [%4];"
                 : "=r"(r0), "=r"(r1), "=r"(r2), "=r"(r3) : "r"(a));
}
__device__ __forceinline__ void ldsm_x4_trans(uint32_t& r0, uint32_t& r1,
                                              uint32_t& r2, uint32_t& r3, uint32_t a) {
    asm volatile("ldmatrix.sync.aligned.m8n8.x4.trans.shared.b16 {%0,%1,%2,%3}, [%4];"
                 : "=r"(r0), "=r"(r1), "=r"(r2), "=r"(r3) : "r"(a));
}
__device__ __forceinline__ void mma_bf16(float* d,
                                         uint32_t a0, uint32_t a1, uint32_t a2, uint32_t a3,
                                         uint32_t b0, uint32_t b1) {
    asm volatile("mma.sync.aligned.m16n8k16.row.col.f32.bf16.bf16.f32 "
                 "{%0,%1,%2,%3}, {%4,%5,%6,%7}, {%8,%9}, {%0,%1,%2,%3};"
                 : "+f"(d[0]), "+f"(d[1]), "+f"(d[2]), "+f"(d[3])
                 : "r"(a0), "r"(a1), "r"(a2), "r"(a3), "r"(b0), "r"(b1));
}
#define CP_ASYNC16(dst, src) \
    asm volatile("cp.async.cg.shared.global [%0], [%1], 16;" :: "r"(dst), "l"(src))
#define CP_COMMIT() asm volatile("cp.async.commit_group;" ::: "memory")
#define CP_WAIT0()  asm volatile("cp.async.wait_group 0;" ::: "memory")
#define CP_WAIT1()  asm volatile("cp.async.wait_group 1;" ::: "memory")

__device__ __forceinline__ void split_bf16(float v, __nv_bfloat16& h, __nv_bfloat16& l) {
    h = __float2bfloat16(v);
    l = __float2bfloat16(v - __bfloat162float(h));
}
__device__ __forceinline__ uint32_t packh(__nv_bfloat16 a, __nv_bfloat16 b) {
    __nv_bfloat162 t; t.x = a; t.y = b;
    return *(uint32_t*)&t;
}
__device__ __forceinline__ void splitpack(float v0, float v1, uint32_t& ph, uint32_t& pl) {
    __nv_bfloat16 h0 = __float2bfloat16(v0), h1 = __float2bfloat16(v1);
    ph = packh(h0, h1);
    float l0 = v0 - __bfloat162float(h0), l1 = v1 - __bfloat162float(h1);
    asm("cvt.rn.bf16x2.f32 %0, %1, %2;" : "=r"(pl) : "f"(l1), "f"(l0));
}
__device__ __forceinline__ float gelu_exact(float v) {
    return 0.5f * v * (1.0f + erff(v * 0.70710678118654752f));
}

// ================= scratch ==================================================
#define MB (1024ull * 1024ull)
__device__ __align__(1024) unsigned char g_scratch[225 * MB];
#define OFF_QH    (0 * MB)
#define OFF_QL    (8 * MB)
#define OFF_KH    (16 * MB)
#define OFF_KL    (24 * MB)
#define OFF_VH    (32 * MB)
#define OFF_VL    (40 * MB)
#define OFF_Y     (48 * MB)
#define OFF_LN1H  (64 * MB)
#define OFF_LN1L  (72 * MB)
#define OFF_ATTH  (80 * MB)
#define OFF_ATTL  (88 * MB)
#define OFF_LN2H  (96 * MB)
#define OFF_LN2L  (104 * MB)
#define OFF_FFH   (112 * MB)
#define OFF_FFL   (144 * MB)
#define OFF_WQKVH (176 * MB)
#define OFF_WQKVL (182 * MB)
#define OFF_WPH   (188 * MB)
#define OFF_WPL   (190 * MB)
#define OFF_W1H   (192 * MB)
#define OFF_W1L   (200 * MB)
#define OFF_W2H   (208 * MB)
#define OFF_W2L   (216 * MB)
#define OFF_BIASC (224 * MB)
#define QKV_SEL_STRIDE 8388608ull

// ================= bias concat ==============================================
__global__ __launch_bounds__(1024) void bias_concat_kernel(
    const float* __restrict__ bq, const float* __restrict__ bk,
    const float* __restrict__ bv, float* __restrict__ dst) {
    int i = threadIdx.x;
    const float* src = (blockIdx.x == 0) ? bq : (blockIdx.x == 1) ? bk : bv;
    dst[blockIdx.x * 1024 + i] = src[i];
}

// ================= fused weight convert+transpose (ALL weights) =============
__global__ __launch_bounds__(256) void wconv_all(
    const float* __restrict__ Wq, const float* __restrict__ Wk,
    const float* __restrict__ Wv, const float* __restrict__ Wp,
    const float* __restrict__ W1, const float* __restrict__ W2,
    __nv_bfloat16* __restrict__ qkvh, __nv_bfloat16* __restrict__ qkvl,
    __nv_bfloat16* __restrict__ wph,  __nv_bfloat16* __restrict__ wpl,
    __nv_bfloat16* __restrict__ w1h,  __nv_bfloat16* __restrict__ w1l,
    __nv_bfloat16* __restrict__ w2h,  __nv_bfloat16* __restrict__ w2l) {
    int bid = blockIdx.x;
    const float* W; __nv_bfloat16 *Wh, *Wl;
    int K, N, bx, by;
    if (bid < 768) {
        int which = bid >> 8;
        int idx = bid & 255;
        W = (which == 0) ? Wq : (which == 1) ? Wk : Wv;
        Wh = qkvh + (size_t)which * 1024 * 1024;
        Wl = qkvl + (size_t)which * 1024 * 1024;
        K = 1024; N = 1024; bx = idx & 15; by = idx >> 4;
    } else if (bid < 1024) {
        int idx = bid - 768;
        W = Wp; Wh = wph; Wl = wpl;
        K = 1024; N = 1024; bx = idx & 15; by = idx >> 4;
    } else if (bid < 2048) {
        int idx = bid - 1024;
        W = W1; Wh = w1h; Wl = w1l;
        K = 1024; N = 4096; bx = idx & 15; by = idx >> 4;
    } else {
        int idx = bid - 2048;
        W = W2; Wh = w2h; Wl = w2l;
        K = 4096; N = 1024; bx = idx & 63; by = idx >> 6;
    }

    __shared__ float t[64][65];
    int k0 = bx * 64, n0 = by * 64;
    int tid = threadIdx.x;
    #pragma unroll
    for (int i = 0; i < 16; i++) {
        int idx = i * 256 + tid;
        int r = idx >> 6, c = idx & 63;
        t[r][c] = W[(size_t)(k0 + r) * N + n0 + c];
    }
    __syncthreads();
    #pragma unroll
    for (int i = 0; i < 16; i++) {
        int idx = i * 256 + tid;
        int r = idx >> 6, c = idx & 63;
        float v = t[c][r];
        __nv_bfloat16 h, l;
        split_bf16(v, h, l);
        size_t o = (size_t)(n0 + r) * K + k0 + c;
        Wh[o] = h; Wl[o] = l;
    }
}

// ================= layernorm -> bf16 hi/lo ==================================
__global__ __launch_bounds__(256) void ln_kernel(const float* __restrict__ x,
                                                 const float* __restrict__ g,
                                                 const float* __restrict__ b,
                                                 __nv_bfloat16* __restrict__ H,
                                                 __nv_bfloat16* __restrict__ L) {
    int row = blockIdx.x;
    int t = threadIdx.x;
    const float4* xr = (const float4*)(x + (size_t)row * CDIM);
    float4 xv = xr[t];
    float s  = xv.x + xv.y + xv.z + xv.w;
    float ss = xv.x * xv.x + xv.y * xv.y + xv.z * xv.z + xv.w * xv.w;
    #pragma unroll
    for (int m = 16; m; m >>= 1) {
        s  += __shfl_xor_sync(0xffffffffu, s,  m);
        ss += __shfl_xor_sync(0xffffffffu, ss, m);
    }
    __shared__ float rs[8], rss[8];
    int warp = t >> 5, lane = t & 31;
    if (lane == 0) { rs[warp] = s; rss[warp] = ss; }
    __syncthreads();
    float tot = 0.f, tots = 0.f;
    #pragma unroll
    for (int i = 0; i < 8; i++) { tot += rs[i]; tots += rss[i]; }
    float mu  = tot * (1.0f / CDIM);
    float var = tots * (1.0f / CDIM) - mu * mu;
    float inv = rsqrtf(var + 1e-5f);
    float4 gv = ((const float4*)g)[t];
    float4 bv = ((const float4*)b)[t];
    float o0 = (xv.x - mu) * inv * gv.x + bv.x;
    float o1 = (xv.y - mu) * inv * gv.y + bv.y;
    float o2 = (xv.z - mu) * inv * gv.z + bv.z;
    float o3 = (xv.w - mu) * inv * gv.w + bv.w;
    __nv_bfloat16 h0, h1, h2, h3, l0, l1, l2, l3;
    split_bf16(o0, h0, l0); split_bf16(o1, h1, l1);
    split_bf16(o2, h2, l2); split_bf16(o3, h3, l3);
    __nv_bfloat162* Hp = (__nv_bfloat162*)(H + (size_t)row * CDIM + t * 4);
    __nv_bfloat162* Lp = (__nv_bfloat162*)(L + (size_t)row * CDIM + t * 4);
    __nv_bfloat162 a01; a01.x = h0; a01.y = h1;
    __nv_bfloat162 a23; a23.x = h2; a23.y = h3;
    __nv_bfloat162 b01; b01.x = l0; b01.y = l1;
    __nv_bfloat162 b23; b23.x = l2; b23.y = l3;
    Hp[0] = a01; Hp[1] = a23;
    Lp[0] = b01; Lp[1] = b23;
}

// ================= HMMA bf16x3 GEMM (R11 config: 2-stage, 2 CTA/SM) =========
#define TSTR 80
#define TILE_B (128 * TSTR)
#define BUF_B  (4 * TILE_B)
#define GEMM_SMEM (2 * BUF_B)

__global__ __launch_bounds__(256, 2) void gemm_tc(
    const __nv_bfloat16* __restrict__ Ah, const __nv_bfloat16* __restrict__ Al,
    const __nv_bfloat16* __restrict__ Bh, const __nv_bfloat16* __restrict__ Bl,
    const float* __restrict__ bias, const float* __restrict__ R,
    float* __restrict__ outF, __nv_bfloat16* __restrict__ outH,
    __nv_bfloat16* __restrict__ outL, int K, int N, int act, int qkv) {
    extern __shared__ char sm[];
    uint32_t sbase = smem_to_u32(sm);
    int tid = threadIdx.x;
    int wid = tid >> 5, lane = tid & 31;
    int warp_m = wid & 3, warp_n = wid >> 2;
    int bx = blockIdx.x;
    int wrow0 = bx * 128;
    int n0 = qkv ? ((bx & 7) * 128) : wrow0;
    const float* biasP = bias + (qkv ? bx * 128 : n0);
    size_t osel = qkv ? (size_t)(bx >> 3) * QKV_SEL_STRIDE : 0;
    int m0 = blockIdx.y * 128;
    int NC = K >> 5;

    float acc[2][8][4];
    #pragma unroll
    for (int i = 0; i < 2; i++)
        #pragma unroll
        for (int j = 0; j < 8; j++)
            #pragma unroll
            for (int c = 0; c < 4; c++) acc[i][j][c] = 0.f;

    const __nv_bfloat16* tiles[4] = {Ah, Al, Bh, Bl};
    int row0s[4] = {m0, m0, wrow0, wrow0};
    int ldr = tid >> 2;
    int ldc = tid & 3;

    #pragma unroll
    for (int t = 0; t < 4; t++)
        #pragma unroll
        for (int it = 0; it < 2; it++) {
            int r = it * 64 + ldr;
            uint32_t dst = sbase + t * TILE_B + r * TSTR + ldc * 16;
            const __nv_bfloat16* src = tiles[t] + (size_t)(row0s[t] + r) * K + ldc * 8;
            CP_ASYNC16(dst, src);
        }
    CP_COMMIT();
    CP_WAIT0();
    __syncthreads();

    int a_row = (lane & 7) + ((lane >> 3) & 1) * 8;
    int a_kb  = ((lane >> 4) & 1) * 16;
    int b_row = (lane & 7) + ((lane >> 4) & 1) * 8;
    int b_kb  = ((lane >> 3) & 1) * 16;

    for (int kc = 0; kc < NC; kc++) {
        int b = kc & 1;
        uint32_t sbuf = sbase + b * BUF_B;
        if (kc + 1 < NC) {
            uint32_t dbuf = sbase + (b ^ 1) * BUF_B;
            int k0 = (kc + 1) * 32;
            #pragma unroll
            for (int t = 0; t < 4; t++)
                #pragma unroll
                for (int it = 0; it < 2; it++) {
                    int r = it * 64 + ldr;
                    uint32_t dst = dbuf + t * TILE_B + r * TSTR + ldc * 16;
                    const __nv_bfloat16* src = tiles[t] + (size_t)(row0s[t] + r) * K + k0 + ldc * 8;
                    CP_ASYNC16(dst, src);
                }
            CP_COMMIT();
        }

        #pragma unroll
        for (int ks = 0; ks < 2; ks++) {
            int kb = ks * 32;
            uint32_t ah[2][4], al[2][4];
            #pragma unroll
            for (int mt = 0; mt < 2; mt++) {
                uint32_t addr = sbuf + (warp_m * 32 + mt * 16 + a_row) * TSTR + kb + a_kb;
                ldsm_x4(ah[mt][0], ah[mt][1], ah[mt][2], ah[mt][3], addr);
                ldsm_x4(al[mt][0], al[mt][1], al[mt][2], al[mt][3], addr + TILE_B);
            }
            #pragma unroll
            for (int nb = 0; nb < 4; nb++) {
                uint32_t addr = sbuf + 2 * TILE_B +
                                (warp_n * 64 + nb * 16 + b_row) * TSTR + kb + b_kb;
                uint32_t bh0, bh1, bh2, bh3, bl0, bl1, bl2, bl3;
                ldsm_x4(bh0, bh1, bh2, bh3, addr);
                ldsm_x4(bl0, bl1, bl2, bl3, addr + TILE_B);
                #pragma unroll
                for (int mt = 0; mt < 2; mt++) {
                    float* e = acc[mt][nb * 2];
                    float* o = acc[mt][nb * 2 + 1];
                    mma_bf16(e, ah[mt][0], ah[mt][1], ah[mt][2], ah[mt][3], bh0, bh1);
                    mma_bf16(e, ah[mt][0], ah[mt][1], ah[mt][2], ah[mt][3], bl0, bl1);
                    mma_bf16(e, al[mt][0], al[mt][1], al[mt][2], al[mt][3], bh0, bh1);
                    mma_bf16(o, ah[mt][0], ah[mt][1], ah[mt][2], ah[mt][3], bh2, bh3);
                    mma_bf16(o, ah[mt][0], ah[mt][1], ah[mt][2], ah[mt][3], bl2, bl3);
                    mma_bf16(o, al[mt][0], al[mt][1], al[mt][2], al[mt][3], bh2, bh3);
                }
            }
        }
        if (kc + 1 < NC) CP_WAIT0();
        __syncthreads();
    }

    #pragma unroll
    for (int mt = 0; mt < 2; mt++) {
        #pragma unroll
        for (int nt = 0; nt < 8; nt++) {
            int cl = warp_n * 64 + nt * 8 + (lane & 3) * 2;
            int col = n0 + cl;
            #pragma unroll
            for (int half = 0; half < 2; half++) {
                int row = m0 + warp_m * 32 + mt * 16 + (lane >> 2) + half * 8;
                float v0 = acc[mt][nt][half * 2 + 0] + biasP[cl + 0];
                float v1 = acc[mt][nt][half * 2 + 1] + biasP[cl + 1];
                if (outF) {
                    if (R) {
                        const float2 rv = *(const float2*)(R + (size_t)row * N + col);
                        v0 += rv.x; v1 += rv.y;
                    }
                    float2 o2; o2.x = v0; o2.y = v1;
                    *(float2*)(outF + (size_t)row * N + col) = o2;
                } else {
                    if (act) { v0 = gelu_exact(v0); v1 = gelu_exact(v1); }
                    __nv_bfloat16 h0, h1, l0, l1;
                    split_bf16(v0, h0, l0);
                    split_bf16(v1, h1, l1);
                    __nv_bfloat162 hh; hh.x = h0; hh.y = h1;
                    __nv_bfloat162 ll; ll.x = l0; ll.y = l1;
                    *(__nv_bfloat162*)(outH + osel + (size_t)row * N + col) = hh;
                    *(__nv_bfloat162*)(outL + osel + (size_t)row * N + col) = ll;
                }
            }
        }
    }
}

// ================= HMMA flash attention (double-buffered K/V) ===============
// Q smem region (36,864 B) is reused as K/V stage A after fragment extraction.
#define ATS 144
#define KV_TILE (64 * ATS)          // 9216
#define KV_STAGE (4 * KV_TILE)      // 36864
#define ATTN_SMEM (2 * KV_STAGE)    // 73728

__global__ __launch_bounds__(256) void attn_tc(
    const __nv_bfloat16* __restrict__ qh, const __nv_bfloat16* __restrict__ ql,
    const __nv_bfloat16* __restrict__ kh, const __nv_bfloat16* __restrict__ kl,
    const __nv_bfloat16* __restrict__ vh, const __nv_bfloat16* __restrict__ vl,
    __nv_bfloat16* __restrict__ oh, __nv_bfloat16* __restrict__ ol) {
    extern __shared__ char sm[];
    uint32_t sb = smem_to_u32(sm);
    uint32_t stA = sb;               // Q region, then KV stage for odd kt
    uint32_t stB = sb + KV_STAGE;    // KV stage for even kt
    uint32_t sQh = stA;              // 128 x 144
    uint32_t sQl = stA + 128 * ATS;

    int qb = gridDim.x - 1 - blockIdx.x;   // LPT
    int bh = blockIdx.y;
    int b = bh >> 4, h = bh & 15;
    int q0 = qb * 128;
    int tid = threadIdx.x, wid = tid >> 5, lane = tid & 31;
    int g = lane >> 2, t4 = lane & 3;

    size_t base = ((size_t)b * TSEQ) * CDIM + (size_t)h * HDIM;

    // prologue: Q -> stage A (group 0)
    #pragma unroll
    for (int i = 0; i < 4; i++) {
        int idx = i * 256 + tid;
        int r = idx >> 3, c = idx & 7;
        size_t gsrc = base + (size_t)(q0 + r) * CDIM + c * 8;
        CP_ASYNC16(sQh + r * ATS + c * 16, qh + gsrc);
        CP_ASYNC16(sQl + r * ATS + c * 16, ql + gsrc);
    }
    CP_COMMIT();
    // KV(0) -> stage B (group 1)
    #pragma unroll
    for (int i = 0; i < 2; i++) {
        int idx = i * 256 + tid;
        int r = idx >> 3, c = idx & 7;
        size_t gsrc = base + (size_t)(r) * CDIM + c * 8;
        uint32_t so = r * ATS + c * 16;
        CP_ASYNC16(stB + so,               kh + gsrc);
        CP_ASYNC16(stB + KV_TILE + so,     kl + gsrc);
        CP_ASYNC16(stB + 2 * KV_TILE + so, vh + gsrc);
        CP_ASYNC16(stB + 3 * KV_TILE + so, vl + gsrc);
    }
    CP_COMMIT();
    CP_WAIT1();        // Q landed (KV0 may be in flight)
    __syncthreads();

    int a_row = (lane & 7) + ((lane >> 3) & 1) * 8;
    int a_kb  = ((lane >> 4) & 1) * 16;
    int b_row = (lane & 7) + ((lane >> 4) & 1) * 8;
    int b_kb  = ((lane >> 3) & 1) * 16;
    int v_row = (lane & 7) + ((lane >> 3) & 1) * 8;
    int v_cb  = ((lane >> 4) & 1) * 16;

    uint32_t qfh[4][4], qfl[4][4];
    #pragma unroll
    for (int ks = 0; ks < 4; ks++) {
        uint32_t ad = sQh + (wid * 16 + a_row) * ATS + ks * 32 + a_kb;
        ldsm_x4(qfh[ks][0], qfh[ks][1], qfh[ks][2], qfh[ks][3], ad);
        ldsm_x4(qfl[ks][0], qfl[ks][1], qfl[ks][2], qfl[ks][3], ad + 128 * ATS);
    }

    float oacc[8][4];
    #pragma unroll
    for (int i = 0; i < 8; i++)
        #pragma unroll
        for (int c = 0; c < 4; c++) oacc[i][c] = 0.f;
    float mrun0 = -1e30f, mrun1 = -1e30f, lrun0 = 0.f, lrun1 = 0.f;

    int nkt = 2 * qb + 2;
    for (int kt = 0; kt < nkt; kt++) {
        uint32_t st = (kt & 1) ? stA : stB;
        CP_WAIT0();            // KV(kt) landed
        __syncthreads();       // all warps done with the other stage / Q frags
        if (kt + 1 < nkt) {    // prefetch KV(kt+1) into the other stage
            uint32_t dst = (kt & 1) ? stB : stA;
            #pragma unroll
            for (int i = 0; i < 2; i++) {
                int idx = i * 256 + tid;
                int r = idx >> 3, c = idx & 7;
                size_t gsrc = base + (size_t)((kt + 1) * 64 + r) * CDIM + c * 8;
                uint32_t so = r * ATS + c * 16;
                CP_ASYNC16(dst + so,               kh + gsrc);
                CP_ASYNC16(dst + KV_TILE + so,     kl + gsrc);
                CP_ASYNC16(dst + 2 * KV_TILE + so, vh + gsrc);
                CP_ASYNC16(dst + 3 * KV_TILE + so, vl + gsrc);
            }
            CP_COMMIT();
        }
        uint32_t sKh = st, sKl = st + KV_TILE;
        uint32_t sVh = st + 2 * KV_TILE, sVl = st + 3 * KV_TILE;

        float sacc[8][4];
        #pragma unroll
        for (int i = 0; i < 8; i++)
            #pragma unroll
            for (int c = 0; c < 4; c++) sacc[i][c] = 0.f;

        #pragma unroll
        for (int kg = 0; kg < 4; kg++) {
            #pragma unroll
            for (int ks = 0; ks < 4; ks++) {
                uint32_t ad = sKh + (kg * 16 + b_row) * ATS + ks * 32 + b_kb;
                uint32_t kh0, kh1, kh2, kh3, kl0, kl1, kl2, kl3;
                ldsm_x4(kh0, kh1, kh2, kh3, ad);
                ldsm_x4(kl0, kl1, kl2, kl3, ad + KV_TILE);
                float* e = sacc[kg * 2];
                float* o = sacc[kg * 2 + 1];
                mma_bf16(e, qfh[ks][0], qfh[ks][1], qfh[ks][2], qfh[ks][3], kh0, kh1);
                mma_bf16(e, qfh[ks][0], qfh[ks][1], qfh[ks][2], qfh[ks][3], kl0, kl1);
                mma_bf16(e, qfl[ks][0], qfl[ks][1], qfl[ks][2], qfl[ks][3], kh0, kh1);
                mma_bf16(o, qfh[ks][0], qfh[ks][1], qfh[ks][2], qfh[ks][3], kh2, kh3);
                mma_bf16(o, qfh[ks][0], qfh[ks][1], qfh[ks][2], qfh[ks][3], kl2, kl3);
                mma_bf16(o, qfl[ks][0], qfl[ks][1], qfl[ks][2], qfl[ks][3], kh2, kh3);
            }
        }

        int r0g = q0 + wid * 16 + g;
        int r1g = r0g + 8;
        bool maskt = (kt >= 2 * qb);
        #pragma unroll
        for (int nt = 0; nt < 8; nt++) {
            #pragma unroll
            for (int c = 0; c < 4; c++) sacc[nt][c] *= 0.125f;
            if (maskt) {
                int cb = kt * 64 + nt * 8 + 2 * t4;
                if (cb     > r0g) sacc[nt][0] = -1e30f;
                if (cb + 1 > r0g) sacc[nt][1] = -1e30f;
                if (cb     > r1g) sacc[nt][2] = -1e30f;
                if (cb + 1 > r1g) sacc[nt][3] = -1e30f;
            }
        }

        float mt0 = -1e30f, mt1 = -1e30f;
        #pragma unroll
        for (int nt = 0; nt < 8; nt++) {
            mt0 = fmaxf(mt0, fmaxf(sacc[nt][0], sacc[nt][1]));
            mt1 = fmaxf(mt1, fmaxf(sacc[nt][2], sacc[nt][3]));
        }
        mt0 = fmaxf(mt0, __shfl_xor_sync(0xffffffffu, mt0, 1));
        mt0 = fmaxf(mt0, __shfl_xor_sync(0xffffffffu, mt0, 2));
        mt1 = fmaxf(mt1, __shfl_xor_sync(0xffffffffu, mt1, 1));
        mt1 = fmaxf(mt1, __shfl_xor_sync(0xffffffffu, mt1, 2));

        float mn0 = fmaxf(mrun0, mt0), mn1 = fmaxf(mrun1, mt1);
        float cr0 = __expf(mrun0 - mn0), cr1 = __expf(mrun1 - mn1);
        mrun0 = mn0; mrun1 = mn1;
        #pragma unroll
        for (int nt = 0; nt < 8; nt++) {
            oacc[nt][0] *= cr0; oacc[nt][1] *= cr0;
            oacc[nt][2] *= cr1; oacc[nt][3] *= cr1;
        }
        lrun0 *= cr0; lrun1 *= cr1;

        float ls0 = 0.f, ls1 = 0.f;
        #pragma unroll
        for (int nt = 0; nt < 8; nt++) {
            sacc[nt][0] = __expf(sacc[nt][0] - mn0);
            sacc[nt][1] = __expf(sacc[nt][1] - mn0);
            sacc[nt][2] = __expf(sacc[nt][2] - mn1);
            sacc[nt][3] = __expf(sacc[nt][3] - mn1);
            ls0 += sacc[nt][0] + sacc[nt][1];
            ls1 += sacc[nt][2] + sacc[nt][3];
        }
        ls0 += __shfl_xor_sync(0xffffffffu, ls0, 1);
        ls0 += __shfl_xor_sync(0xffffffffu, ls0, 2);
        ls1 += __shfl_xor_sync(0xffffffffu, ls1, 1);
        ls1 += __shfl_xor_sync(0xffffffffu, ls1, 2);
        lrun0 += ls0; lrun1 += ls1;

        #pragma unroll
        for (int s = 0; s < 4; s++) {
            uint32_t aPh[4], aPl[4];
            splitpack(sacc[2 * s][0],     sacc[2 * s][1],     aPh[0], aPl[0]);
            splitpack(sacc[2 * s][2],     sacc[2 * s][3],     aPh[1], aPl[1]);
            splitpack(sacc[2 * s + 1][0], sacc[2 * s + 1][1], aPh[2], aPl[2]);
            splitpack(sacc[2 * s + 1][2], sacc[2 * s + 1][3], aPh[3], aPl[3]);
            #pragma unroll
            for (int p = 0; p < 4; p++) {
                uint32_t ad = sVh + (s * 16 + v_row) * ATS + p * 32 + v_cb;
                uint32_t vh0, vh1, vh2, vh3, vl0, vl1, vl2, vl3;
                ldsm_x4_trans(vh0, vh1, vh2, vh3, ad);
                ldsm_x4_trans(vl0, vl1, vl2, vl3, ad + KV_TILE);
                float* e = oacc[p * 2];
                float* o = oacc[p * 2 + 1];
                mma_bf16(e, aPh[0], aPh[1], aPh[2], aPh[3], vh0, vh1);
                mma_bf16(e, aPl[0], aPl[1], aPl[2], aPl[3], vh0, vh1);
                mma_bf16(e, aPh[0], aPh[1], aPh[2], aPh[3], vl0, vl1);
                mma_bf16(o, aPh[0], aPh[1], aPh[2], aPh[3], vh2, vh3);
                mma_bf16(o, aPl[0], aPl[1], aPl[2], aPl[3], vh2, vh3);
                mma_bf16(o, aPh[0], aPh[1], aPh[2], aPh[3], vl2, vl3);
            }
        }
    }

    float il0 = 1.0f / lrun0, il1 = 1.0f / lrun1;
    int r0g = q0 + wid * 16 + g;
    #pragma unroll
    for (int nt = 0; nt < 8; nt++) {
        int col = nt * 8 + 2 * t4;
        float v0 = oacc[nt][0] * il0, v1 = oacc[nt][1] * il0;
        float v2 = oacc[nt][2] * il1, v3 = oacc[nt][3] * il1;
        __nv_bfloat16 h0, h1, h2, h3, l0, l1, l2, l3;
        split_bf16(v0, h0, l0); split_bf16(v1, h1, l1);
        split_bf16(v2, h2, l2); split_bf16(v3, h3, l3);
        size_t o0 = base + (size_t)r0g * CDIM + col;
        size_t o1 = base + (size_t)(r0g + 8) * CDIM + col;
        __nv_bfloat162 t;
        t.x = h0; t.y = h1; *(__nv_bfloat162*)(oh + o0) = t;
        t.x = l0; t.y = l1; *(__nv_bfloat162*)(ol + o0) = t;
        t.x = h2; t.y = h3; *(__nv_bfloat162*)(oh + o1) = t;
        t.x = l2; t.y = l3; *(__nv_bfloat162*)(ol + o1) = t;
    }
}

// ================= launch ====================================================
extern "C" void kernel_launch(void* const* d_in, const int* in_sizes, int n_in,
                              void* d_out, int out_size) {
    const float* x   = (const float*)d_in[0];
    const float* Wq  = (const float*)d_in[1];
    const float* bq  = (const float*)d_in[2];
    const float* Wk  = (const float*)d_in[3];
    const float* bk  = (const float*)d_in[4];
    const float* Wv  = (const float*)d_in[5];
    const float* bv  = (const float*)d_in[6];
    const float* Wp  = (const float*)d_in[7];
    const float* bp  = (const float*)d_in[8];
    const float* W1  = (const float*)d_in[9];
    const float* b1  = (const float*)d_in[10];
    const float* W2  = (const float*)d_in[11];
    const float* b2  = (const float*)d_in[12];
    const float* g1  = (const float*)d_in[13];
    const float* be1 = (const float*)d_in[14];
    const float* g2  = (const float*)d_in[15];
    const float* be2 = (const float*)d_in[16];
    float* out = (float*)d_out;

    unsigned char* S;
    cudaGetSymbolAddress((void**)&S, g_scratch);
    __nv_bfloat16* qhB = (__nv_bfloat16*)(S + OFF_QH);
    __nv_bfloat16* qlB = (__nv_bfloat16*)(S + OFF_QL);
    __nv_bfloat16* khB = (__nv_bfloat16*)(S + OFF_KH);
    __nv_bfloat16* klB = (__nv_bfloat16*)(S + OFF_KL);
    __nv_bfloat16* vhB = (__nv_bfloat16*)(S + OFF_VH);
    __nv_bfloat16* vlB = (__nv_bfloat16*)(S + OFF_VL);
    float* yb  = (float*)(S + OFF_Y);
    __nv_bfloat16* ln1h = (__nv_bfloat16*)(S + OFF_LN1H);
    __nv_bfloat16* ln1l = (__nv_bfloat16*)(S + OFF_LN1L);
    __nv_bfloat16* atth = (__nv_bfloat16*)(S + OFF_ATTH);
    __nv_bfloat16* attl = (__nv_bfloat16*)(S + OFF_ATTL);
    __nv_bfloat16* ln2h = (__nv_bfloat16*)(S + OFF_LN2H);
    __nv_bfloat16* ln2l = (__nv_bfloat16*)(S + OFF_LN2L);
    __nv_bfloat16* ffh  = (__nv_bfloat16*)(S + OFF_FFH);
    __nv_bfloat16* ffl  = (__nv_bfloat16*)(S + OFF_FFL);
    __nv_bfloat16* wqkvh = (__nv_bfloat16*)(S + OFF_WQKVH);
    __nv_bfloat16* wqkvl = (__nv_bfloat16*)(S + OFF_WQKVL);
    __nv_bfloat16* wph = (__nv_bfloat16*)(S + OFF_WPH);
    __nv_bfloat16* wpl = (__nv_bfloat16*)(S + OFF_WPL);
    __nv_bfloat16* w1h = (__nv_bfloat16*)(S + OFF_W1H);
    __nv_bfloat16* w1l = (__nv_bfloat16*)(S + OFF_W1L);
    __nv_bfloat16* w2h = (__nv_bfloat16*)(S + OFF_W2H);
    __nv_bfloat16* w2l = (__nv_bfloat16*)(S + OFF_W2L);
    float* biasC = (float*)(S + OFF_BIASC);

    cudaFuncSetAttribute(attn_tc, cudaFuncAttributeMaxDynamicSharedMemorySize, ATTN_SMEM);
    cudaFuncSetAttribute(gemm_tc, cudaFuncAttributeMaxDynamicSharedMemorySize, GEMM_SMEM);

    // 1: bias concat
    bias_concat_kernel<<<3, 1024>>>(bq, bk, bv, biasC);
    // 2: all weight conversions
    wconv_all<<<3072, 256>>>(Wq, Wk, Wv, Wp, W1, W2,
                             wqkvh, wqkvl, wph, wpl, w1h, w1l, w2h, w2l);
    // 3: LN1
    ln_kernel<<<NROWS, 256>>>(x, g1, be1, ln1h, ln1l);

    dim3 gQKV(24, 32);
    dim3 gQ(8, 32);
    dim3 gF1(32, 32);
    // 4: QKV
    gemm_tc<<<gQKV, 256, GEMM_SMEM>>>(ln1h, ln1l, wqkvh, wqkvl, biasC, nullptr,
                                      nullptr, qhB, qlB, 1024, 1024, 0, 1);
    // 5: attention
    attn_tc<<<dim3(TSEQ / 128, 4 * NHEADS), 256, ATTN_SMEM>>>(qhB, qlB, khB, klB, vhB, vlB, atth, attl);
    // 6: proj (ncu -s 5 -c 1 lands here)
    gemm_tc<<<gQ, 256, GEMM_SMEM>>>(atth, attl, wph, wpl, bp, x, yb, nullptr, nullptr, 1024, 1024, 0, 0);
    // 7: LN2
    ln_kernel<<<NROWS, 256>>>(yb, g2, be2, ln2h, ln2l);
    // 8: FF1
    gemm_tc<<<gF1, 256, GEMM_SMEM>>>(ln2h, ln2l, w1h, w1l, b1, nullptr, nullptr, ffh, ffl, 1024, 4096, 1, 0);
    // 9: FF2
    gemm_tc<<<gQ, 256, GEMM_SMEM>>>(ffh, ffl, w2h, w2l, b2, yb, out, nullptr, nullptr, 4096, 1024, 0, 0);
}